// round 12
// baseline (speedup 1.0000x reference)
#include <cuda_runtime.h>
#include <math.h>

// Problem constants
#define NB    4
#define NC    17
#define NH    128
#define NW    128
#define HWSZ  (NH*NW)
#define NPC   51
#define NWID  128
#define NSTEP 48
#define ALIVE_IDX 3
#define ALIVE_THR 0.1f

#define CHW   (NC*HWSZ)
#define BCHW  (NB*CHW)
#define FINAL_ELEMS (NB*4*HWSZ)
#define NBLK  148
#define NTHR  256
#define NSTRIP 1024

typedef unsigned long long ull;

// f32x2 packed-pair helpers
#define F2FMA(d, a, b, c) asm("fma.rn.f32x2 %0, %1, %2, %3;" : "=l"(d) : "l"(a), "l"(b), "l"(c))
#define F2MUL2(d, a, b)   asm("mul.rn.f32x2 %0, %1, %2;"     : "=l"(d) : "l"(a), "l"(b))
#define F2ADD(d, a, b)    asm("add.rn.f32x2 %0, %1, %2;"     : "=l"(d) : "l"(a), "l"(b))
#define PK2(d, lo, hi)    asm("mov.b64 %0, {%1, %2};" : "=l"(d) : "f"(lo), "f"(hi))
#define UPK2(lo, hi, s)   asm("mov.b64 {%0, %1}, %2;" : "=f"(lo), "=f"(hi) : "l"(s))

// Static device scratch
__device__ int      g_claim[NSTRIP];          // per-strip claim epoch
__device__ int      g_q[NSTEP + 1][NSTRIP];   // step-indexed worklists
__device__ unsigned g_qn[NSTEP + 1];          // worklist counts
__device__ unsigned g_count;
__device__ volatile unsigned g_sense;

// R7 barrier (nanosleep spin — proven), arrival count = NBLK.
__device__ __forceinline__ void grid_barrier(unsigned target) {
    __syncthreads();
    if (threadIdx.x == 0) {
        __threadfence();
        if (atomicAdd(&g_count, 1u) == NBLK - 1u) {
            g_count = 0u;
            __threadfence();
            g_sense = target;
        } else {
            while (g_sense != target) __nanosleep(32);
            __threadfence();
        }
    }
    __syncthreads();
}

// Dynamic smem layout (ull units)
#define S_W1  0                      // 128 rows x 52 dup W1
#define S_W2  (S_W1 + 128*52)        // 128 rows x 18 dup W2^T
#define S_B1  (S_W2 + 128*18)        // 128 dup b1
#define S_B2  (S_B1 + 128)           // 18 dup b2 (+pad)
#define S_PB  (S_B2 + 20)            // 60 pairs x 54 p-vector buffer
#define PBS   54
#define S_NB  (S_PB + 60*PBS)        // n_ch3 buffer: 6 rows x 20 floats = 60 ull
#define SMEM_ULLS (S_NB + 64)
#define SMEM_BYTES (SMEM_ULLS * 8)

__global__ __launch_bounds__(NTHR, 1)
void nca_persistent(const float* __restrict__ init_state,
                    const float* __restrict__ rnd_all,
                    const float* __restrict__ W1, const float* __restrict__ b1,
                    const float* __restrict__ W2, const float* __restrict__ b2,
                    float* __restrict__ dev_path,   // [48,B,C,H,W] (pre-zeroed)
                    float* __restrict__ final_out)  // [B,4,H,W]   (pre-zeroed)
{
    extern __shared__ ull smem[];
    const int tid  = threadIdx.x;
    const int bid  = blockIdx.x;
    const int lane = tid & 31;

    // ---- load duplicated weights once ----
    for (int i = tid; i < 128 * 52; i += NTHR) {
        int o = i / 52, c = i - o * 52;
        float wv = (c < NPC) ? W1[o * NPC + c] : 0.0f;
        ull d; PK2(d, wv, wv); smem[S_W1 + i] = d;
    }
    for (int i = tid; i < 128 * 18; i += NTHR) {
        int o = i / 18, j = i - o * 18;
        float wv = (j < NC) ? W2[j * NWID + o] : 0.0f;
        ull d; PK2(d, wv, wv); smem[S_W2 + i] = d;
    }
    if (tid < 128) { float wv = b1[tid]; ull d; PK2(d, wv, wv); smem[S_B1 + tid] = d; }
    if (tid < 18)  { float wv = (tid < NC) ? b2[tid] : 0.0f; ull d; PK2(d, wv, wv); smem[S_B2 + tid] = d; }

    int bias_ok = 1;
    if (tid < 128) bias_ok = (b1[tid] <= 0.0f);
    if (tid < NC)  bias_ok = bias_ok && (b2[tid] == 0.0f);
    const int allz = __syncthreads_and(bias_ok);

    // prologue: block 0 resets queue counters + claims (once per replay)
    if (bid == 0) {
        for (int i = tid; i <= NSTEP; i += NTHR) g_qn[i] = 0;
        for (int i = tid; i < NSTRIP; i += NTHR) g_claim[i] = 0;
    }

    // task-local thread mapping: pair pp (0..59), quad mq (0..3)
    int pp = tid >> 2; if (pp > 59) pp = 59;   // dummy threads duplicate pair 59
    const int mq   = tid & 3;
    const int pcol = pp % 10;                  // 0..9 (region cols, 2px each)
    const int prow = pp / 10;                  // 0..5 (region rows)

    float* nbuf = (float*)(smem + S_NB);

    unsigned bsense = 0;
    const float* cur = init_state;

    bsense ^= 1u; grid_barrier(bsense);        // barrier #1 (prologue visible)

    #pragma unroll 1
    for (int t = 0; t < NSTEP; t++) {
        float* dst = dev_path + (size_t)t * BCHW;
        const bool dense = (t == 0) || (!allz);
        const unsigned nq = dense ? NSTRIP : __ldcg(&g_qn[t]);

        #pragma unroll 1
        for (unsigned k = (unsigned)bid; k < nq; k += NBLK) {
            const int e  = dense ? (int)k : __ldcg(&g_q[t][k]);
            const int sb = e >> 8;
            const int rr = e & 255;
            const int rx = rr & 7, ry = rr >> 3;
            const int bx = rx * 16, sy = ry * 4;

            const int x0 = bx + pcol * 2 - 2;   // -2 .. bx+16
            const int y  = sy + prow - 1;       // sy-1 .. sy+4

            // clamped offsets + validity masks (SAME zero-pad for conv)
            int cxo[4]; float cmf[4];
            #pragma unroll
            for (int j = 0; j < 4; j++) {
                int v = x0 - 1 + j;
                cmf[j] = (v >= 0 && v < NW) ? 1.0f : 0.0f;
                cxo[j] = v < 0 ? 0 : (v >= NW ? NW - 1 : v);
            }
            int ryo[3]; float rmf[3];
            #pragma unroll
            for (int i = 0; i < 3; i++) {
                int v = y - 1 + i;
                rmf[i] = (v >= 0 && v < NH) ? 1.0f : 0.0f;
                ryo[i] = (v < 0 ? 0 : (v >= NH ? NH - 1 : v)) * NW;
            }

            ull* pb = smem + S_PB + pp * PBS;
            float moA = -1e30f, moB = -1e30f;   // pre-alive maxpool (ch3, -inf pad)

            // --- conv: channels mq, mq+4, ... ---
            for (int c = mq; c < NC; c += 4) {
                const float* ch = cur + (sb * NC + c) * HWSZ;
                float a[3][4];
                #pragma unroll
                for (int i = 0; i < 3; i++) {
                    #pragma unroll
                    for (int j = 0; j < 4; j++) {
                        float rv = __ldg(ch + ryo[i] + cxo[j]);
                        float m  = rmf[i] * cmf[j];
                        a[i][j] = rv * m;
                        if (c == ALIVE_IDX) {
                            float vm = (m != 0.0f) ? rv : -1e30f;
                            if (j < 3) moA = fmaxf(moA, vm);
                            if (j > 0) moB = fmaxf(moB, vm);
                        }
                    }
                }
                float gxA = ((a[0][2]-a[0][0]) + 2.0f*(a[1][2]-a[1][0]) + (a[2][2]-a[2][0])) * 0.125f;
                float gxB = ((a[0][3]-a[0][1]) + 2.0f*(a[1][3]-a[1][1]) + (a[2][3]-a[2][1])) * 0.125f;
                float gyA = ((a[2][0]-a[0][0]) + 2.0f*(a[2][1]-a[0][1]) + (a[2][2]-a[0][2])) * 0.125f;
                float gyB = ((a[2][1]-a[0][1]) + 2.0f*(a[2][2]-a[0][2]) + (a[2][3]-a[0][3])) * 0.125f;

                ull d;
                PK2(d, a[1][1], a[1][2]); pb[c]      = d;
                PK2(d, gxA, gxB);         pb[17 + c] = d;
                PK2(d, gyA, gyB);         pb[34 + c] = d;

                if (c == 16) {
                    float saA, caA, saB, caB;
                    sincosf(a[1][1], &saA, &caA);
                    sincosf(a[1][2], &saB, &caB);
                    ull ca2, sa2;
                    PK2(ca2, caA, caB); PK2(sa2, saA, saB);
                    pb[51] = 0ULL; pb[52] = ca2; pb[53] = sa2;
                }
            }
            __syncthreads();

            // --- MLP (R7 structure: o = 4*i + mq, 32 iters) ---
            ull p2[52];
            {
                const ulonglong2* pbr = reinterpret_cast<const ulonglong2*>(pb);
                #pragma unroll
                for (int q = 0; q < 26; q++) {
                    ulonglong2 v = pbr[q];
                    p2[2 * q] = v.x; p2[2 * q + 1] = v.y;
                }
                ull ca2 = pb[52], sa2 = pb[53];
                float sA, sB; UPK2(sA, sB, sa2);
                ull nsa2; PK2(nsa2, -sA, -sB);
                #pragma unroll
                for (int c = 0; c < NC; c++) {
                    ull gx2 = p2[17 + c], gy2 = p2[34 + c], u;
                    F2MUL2(u, ca2, gx2); F2FMA(u, sa2, gy2, u);  p2[17 + c] = u;
                    F2MUL2(u, ca2, gy2); F2FMA(u, nsa2, gx2, u); p2[34 + c] = u;
                }
            }

            ull dx2[18];
            #pragma unroll
            for (int j = 0; j < 18; j++)
                dx2[j] = (mq == 0) ? smem[S_B2 + j] : 0ULL;

            #pragma unroll 1
            for (int i = 0; i < 32; i++) {
                const int o = 4 * i + mq;
                ull acc0 = smem[S_B1 + o];
                ull acc1 = 0ULL, acc2 = 0ULL, acc3 = 0ULL;
                const ulonglong2* r = reinterpret_cast<const ulonglong2*>(smem + S_W1 + o * 52);
                #pragma unroll
                for (int q = 0; q < 13; q++) {
                    ulonglong2 wv = r[q];
                    ulonglong2 wu = r[q + 13];
                    F2FMA(acc0, wv.x, p2[2 * q],      acc0);
                    F2FMA(acc1, wv.y, p2[2 * q + 1],  acc1);
                    F2FMA(acc2, wu.x, p2[2 * q + 26], acc2);
                    F2FMA(acc3, wu.y, p2[2 * q + 27], acc3);
                }
                ull s02, s13, hs;
                F2ADD(s02, acc0, acc2); F2ADD(s13, acc1, acc3); F2ADD(hs, s02, s13);
                float hA, hB; UPK2(hA, hB, hs);
                hA = fmaxf(hA, 0.0f); hB = fmaxf(hB, 0.0f);
                ull h2; PK2(h2, hA, hB);

                const ulonglong2* r2 = reinterpret_cast<const ulonglong2*>(smem + S_W2 + o * 18);
                #pragma unroll
                for (int q = 0; q < 9; q++) {
                    ulonglong2 wv = r2[q];
                    F2FMA(dx2[2 * q],     wv.x, h2, dx2[2 * q]);
                    F2FMA(dx2[2 * q + 1], wv.y, h2, dx2[2 * q + 1]);
                }
            }

            #pragma unroll
            for (int j = 0; j < 18; j++) {
                ull o2 = __shfl_down_sync(0xFFFFFFFFu, dx2[j], 2, 4);
                F2ADD(dx2[j], dx2[j], o2);
                o2 = __shfl_down_sync(0xFFFFFFFFu, dx2[j], 1, 4);
                F2ADD(dx2[j], dx2[j], o2);
            }

            // --- mq0: apply stochastic update, publish n_ch3 to smem ---
            if (mq == 0) {
                int xr = x0 < 0 ? 0 : (x0 > NW - 2 ? NW - 2 : x0);
                int yr = y  < 0 ? 0 : (y  > NH - 1 ? NH - 1 : y);
                const float2 rr2 = *reinterpret_cast<const float2*>(
                    rnd_all + ((size_t)t * NB + sb) * HWSZ + yr * NW + xr);
                float mA = (rr2.x < 0.5f) ? 1.0f : 0.0f;
                float mB = (rr2.y < 0.5f) ? 1.0f : 0.0f;
                ull m2; PK2(m2, mA, mB);
                #pragma unroll
                for (int c = 0; c < NC; c++)
                    F2FMA(p2[c], dx2[c], m2, p2[c]);   // p2[c] = new (unmasked)

                float nA3, nB3; UPK2(nA3, nB3, p2[ALIVE_IDX]);
                bool vA = (x0 >= 0) && (x0 < NW) && (y >= 0) && (y < NH);
                bool vB = (x0 + 1 >= 0) && (x0 + 1 < NW) && (y >= 0) && (y < NH);
                nbuf[prow * 20 + pcol * 2]     = vA ? nA3 : -1e30f;
                nbuf[prow * 20 + pcol * 2 + 1] = vB ? nB3 : -1e30f;
            }
            __syncthreads();

            // share pre-alive (computed on mq3) to the quad
            float moAs = __shfl_sync(0xFFFFFFFFu, moA, lane | 3, 32);
            float moBs = __shfl_sync(0xFFFFFFFFu, moB, lane | 3, 32);

            // --- own pixels: post-alive maxpool from nbuf, masked write ---
            bool myAlive = false;
            if (mq == 0 && pcol >= 1 && pcol <= 8 && prow >= 1 && prow <= 4) {
                const int cA = pcol * 2;
                float w0 = -1e30f, w1 = -1e30f, w2 = -1e30f, w3 = -1e30f;
                #pragma unroll
                for (int i = -1; i <= 1; i++) {
                    const float* rowp = nbuf + (prow + i) * 20 + cA;
                    w0 = fmaxf(w0, rowp[-1]); w1 = fmaxf(w1, rowp[0]);
                    w2 = fmaxf(w2, rowp[1]);  w3 = fmaxf(w3, rowp[2]);
                }
                float mnA = fmaxf(fmaxf(w0, w1), w2);
                float mnB = fmaxf(fmaxf(w1, w2), w3);
                bool aliveA = (moAs > ALIVE_THR) && (mnA > ALIVE_THR);
                bool aliveB = (moBs > ALIVE_THR) && (mnB > ALIVE_THR);
                myAlive = aliveA || aliveB;
                if (myAlive) {
                    float fA = aliveA ? 1.0f : 0.0f, fB = aliveB ? 1.0f : 0.0f;
                    ull am2; PK2(am2, fA, fB);
                    float* dout = dst + sb * CHW + y * NW + x0;
                    #pragma unroll
                    for (int c = 0; c < NC; c++) {
                        ull mv; F2MUL2(mv, p2[c], am2);
                        *reinterpret_cast<ull*>(dout + c * HWSZ) = mv;
                    }
                    if (t == NSTEP - 1) {
                        #pragma unroll
                        for (int c = 0; c < 4; c++) {
                            ull mv; F2MUL2(mv, p2[c], am2);
                            *reinterpret_cast<ull*>(final_out + (sb * 4 + c) * HWSZ + y * NW + x0) = mv;
                        }
                    }
                }
            }

            const int anyAlive = __syncthreads_or(myAlive ? 1 : 0);

            // --- enqueue t+1: claims + warp-aggregated append (warp 0 only) ---
            if (allz && t < NSTEP - 1 && anyAlive && tid < 32) {
                bool claimed = false; int ns = 0;
                if (lane < 9) {
                    int nry = ry + lane / 3 - 1;
                    int nrx = rx + lane % 3 - 1;
                    if (nry >= 0 && nry < 32 && nrx >= 0 && nrx < 8) {
                        ns = sb * 256 + nry * 8 + nrx;
                        claimed = (atomicExch(&g_claim[ns], t + 1) != t + 1);
                    }
                }
                unsigned bal = __ballot_sync(0xFFFFFFFFu, claimed);
                unsigned idxbase = 0;
                if (lane == 0 && bal)
                    idxbase = atomicAdd(&g_qn[t + 1], (unsigned)__popc(bal));
                idxbase = __shfl_sync(0xFFFFFFFFu, idxbase, 0);
                if (claimed) {
                    int rank = __popc(bal & ((1u << lane) - 1u));
                    g_q[t + 1][idxbase + rank] = ns;
                }
            }
        }

        bsense ^= 1u; grid_barrier(bsense);    // ONE barrier per step
        cur = dst;
    }

    bsense ^= 1u; grid_barrier(bsense);        // epilogue: even total (50)
}

// ---------------------------------------------------------------------------
// Inputs: 0 init_state [4,17,128,128], 1 rand [48,4,1,128,128],
//         2 W1 [128,51], 3 b1 [128], 4 W2 [17,128], 5 b2 [17]
// Output f32: final[:, :4] (262144) then dev_path (48*4*17*128*128).
// ---------------------------------------------------------------------------
extern "C" void kernel_launch(void* const* d_in, const int* in_sizes, int n_in,
                              void* d_out, int out_size)
{
    const float* init_state = (const float*)d_in[0];
    const float* rnd        = (const float*)d_in[1];
    const float* W1         = (const float*)d_in[2];
    const float* b1         = (const float*)d_in[3];
    const float* W2         = (const float*)d_in[4];
    const float* b2         = (const float*)d_in[5];

    float* out      = (float*)d_out;
    float* final_p  = out;
    float* dev_path = out + FINAL_ELEMS;

    cudaMemsetAsync(d_out, 0, (size_t)out_size * sizeof(float));

    cudaFuncSetAttribute(nca_persistent,
                         cudaFuncAttributeMaxDynamicSharedMemorySize, SMEM_BYTES);

    nca_persistent<<<NBLK, NTHR, SMEM_BYTES>>>(init_state, rnd, W1, b1, W2, b2,
                                               dev_path, final_p);
}

// round 13
// speedup vs baseline: 1.3273x; 1.3273x over previous
#include <cuda_runtime.h>
#include <math.h>

// Problem constants
#define NB    4
#define NC    17
#define NH    128
#define NW    128
#define HWSZ  (NH*NW)
#define NPC   51
#define NWID  128
#define NSTEP 48
#define ALIVE_IDX 3
#define ALIVE_THR 0.1f

#define CHW   (NC*HWSZ)
#define BCHW  (NB*CHW)
#define FINAL_ELEMS (NB*4*HWSZ)
#define NBLK  256
#define NGRP  16

typedef unsigned long long ull;

// f32x2 packed-pair helpers
#define F2FMA(d, a, b, c) asm("fma.rn.f32x2 %0, %1, %2, %3;" : "=l"(d) : "l"(a), "l"(b), "l"(c))
#define F2MUL2(d, a, b)   asm("mul.rn.f32x2 %0, %1, %2;"     : "=l"(d) : "l"(a), "l"(b))
#define F2ADD(d, a, b)    asm("add.rn.f32x2 %0, %1, %2;"     : "=l"(d) : "l"(a), "l"(b))
#define PK2(d, lo, hi)    asm("mov.b64 %0, {%1, %2};" : "=l"(d) : "f"(lo), "f"(hi))
#define UPK2(lo, hi, s)   asm("mov.b64 {%0, %1}, %2;" : "=f"(lo), "=f"(hi) : "l"(s))

// Static device scratch
__device__ float         g_alive[NB * HWSZ];   // unmasked new alive channel
__device__ unsigned char g_amask[NB * HWSZ];   // per-pixel alive map (post-mask)
__device__ unsigned      g_c1[NGRP * 32];      // tree barrier level-1 (128B padded)
__device__ unsigned      g_c2;                 // tree barrier root
__device__ volatile unsigned g_sense;

// Two-level tree barrier: 16 groups x 16 blocks; nanosleep wait (proven).
__device__ __forceinline__ void grid_barrier(unsigned target) {
    __syncthreads();
    if (threadIdx.x == 0) {
        const unsigned g = blockIdx.x & (NGRP - 1);
        __threadfence();
        if (atomicAdd(&g_c1[g * 32], 1u) == 15u) {
            g_c1[g * 32] = 0u;
            __threadfence();
            if (atomicAdd(&g_c2, 1u) == NGRP - 1u) {
                g_c2 = 0u;
                __threadfence();
                g_sense = target;
            }
        }
        while (g_sense != target) __nanosleep(32);
        __threadfence();
    }
    __syncthreads();
}

// Dynamic smem layout (ull units)
#define S_W1  0                      // 128 rows x 52 dup W1
#define S_W2  (S_W1 + 128*52)        // 128 rows x 18 dup W2^T
#define S_B1  (S_W2 + 128*18)        // 128 dup b1
#define S_B2  (S_B1 + 128)           // 18 dup b2
#define S_PB  (S_B2 + 20)            // 32 pairs x 54 p-vector buffer
#define PBS   54
#define SMEM_ULLS (S_PB + 32*PBS)
#define SMEM_BYTES (SMEM_ULLS * 8)

__global__ __launch_bounds__(128, 2)
void nca_persistent(const float* __restrict__ init_state,
                    const float* __restrict__ rnd_all,
                    const float* __restrict__ W1, const float* __restrict__ b1,
                    const float* __restrict__ W2, const float* __restrict__ b2,
                    float* __restrict__ dev_path,   // [48,B,C,H,W] (pre-zeroed)
                    float* __restrict__ final_out)  // [B,4,H,W]   (pre-zeroed)
{
    extern __shared__ ull smem[];
    __shared__ int sActive[4];
    const int tid = threadIdx.x;

    // ---- load duplicated weights once (R7 verbatim) ----
    for (int i = tid; i < 128 * 52; i += 128) {
        int o = i / 52, c = i - o * 52;
        float wv = (c < NPC) ? W1[o * NPC + c] : 0.0f;
        ull d; PK2(d, wv, wv); smem[S_W1 + i] = d;
    }
    for (int i = tid; i < 128 * 18; i += 128) {
        int o = i / 18, j = i - o * 18;
        float wv = (j < NC) ? W2[j * NWID + o] : 0.0f;
        ull d; PK2(d, wv, wv); smem[S_W2 + i] = d;
    }
    { float wv = b1[tid]; ull d; PK2(d, wv, wv); smem[S_B1 + tid] = d; }
    if (tid < 18) { float wv = (tid < NC) ? b2[tid] : 0.0f; ull d; PK2(d, wv, wv); smem[S_B2 + tid] = d; }

    int bias_ok = (b1[tid] <= 0.0f);
    if (tid < NC) bias_ok = bias_ok && (b2[tid] == 0.0f);
    const int allz = __syncthreads_and(bias_ok);

    // ---- batch-interleaved strip ownership ----
    // Warp w of block bid owns strip (batch = w, r = (bid - 64*w) & 255).
    // The 4 batches' (identical-location) blobs map to disjoint block ranges,
    // so every active block carries <= 1 active strip.
    const int bid  = blockIdx.x;
    const int w    = tid >> 5;
    const int lane = tid & 31;

    const int orr  = (bid - 64 * w) & 255;   // own strip index (row-major)
    const int osrx = orr & 7;                // strip col 0..7
    const int osry = orr >> 3;               // strip row 0..31
    const int obx0 = osrx * 16;
    const int osy0 = osry * 4;

    // own-strip pixel mapping: 32 lanes x 1 pair (8 pair-cols x 4 rows)
    const int opr = lane & 7, oly = lane >> 3;
    const int ox0 = obx0 + opr * 2;
    const int oy  = osy0 + oly;
    const int opix = oy * NW + ox0;

    // cooperative mapping for A2: pair 0..31, quad 0..3
    const int mpair = tid >> 2, mq = tid & 3;
    const int mpr = mpair & 7, mply = mpair >> 3;

    unsigned bsense = 0;
    const float* cur = init_state;

    #pragma unroll 1
    for (int t = 0; t < NSTEP; t++) {
        float* dst = dev_path + (size_t)t * BCHW;

        // ========== PHASE A1: per-warp skip check (own strip) ==========
        bool skipped = false;
        if (t > 0 && allz) {
            // 18x6 alive-map halo of own strip
            const int hx0 = obx0 - 1, hy0 = osy0 - 1;
            unsigned v = 0;
            #pragma unroll
            for (int k = 0; k < 4; k++) {
                int i = lane + 32 * k;
                if (i < 108) {
                    int hx = hx0 + (i % 18);
                    int hy = hy0 + (i / 18);
                    if (hx >= 0 && hx < NW && hy >= 0 && hy < NH)
                        v |= __ldcg(&g_amask[w * HWSZ + hy * NW + hx]);
                }
            }
            skipped = !__any_sync(0xFFFFFFFFu, v != 0);
        }
        if (lane == 0) sActive[w] = skipped ? 0 : 1;
        if (skipped) {
            *reinterpret_cast<ull*>(&g_alive[w * HWSZ + opix]) = 0ULL;
            uchar2 z; z.x = 0; z.y = 0;
            *reinterpret_cast<uchar2*>(&g_amask[w * HWSZ + opix]) = z;
        }
        __syncthreads();

        // ========== PHASE A2: cooperative compute of active strips ==========
        #pragma unroll 1
        for (int s = 0; s < 4; s++) {
            if (!sActive[s]) continue;
            const int sb   = s;
            const int sr   = (bid - 64 * s) & 255;
            const int sbx0 = (sr & 7) * 16;
            const int ssy0 = (sr >> 3) * 4;

            const int mx0  = sbx0 + mpr * 2;
            const int my   = ssy0 + mply;
            const int mpix = my * NW + mx0;
            ull* pb = smem + S_PB + mpair * PBS;

            // --- cooperative conv: 4 threads/pair, channels mq,mq+4,... ---
            {
                const int xm1 = (mx0 >= 1) ? mx0 - 1 : 0;
                const int xp2 = (mx0 + 2 < NW) ? mx0 + 2 : NW - 1;
                const int ym1 = (my >= 1) ? my - 1 : 0;
                const int yp1 = (my + 1 < NH) ? my + 1 : NH - 1;
                const int oy0 = ym1 * NW, oy1 = my * NW, oy2 = yp1 * NW;
                const float fy0 = (my >= 1) ? 1.0f : 0.0f;
                const float fy2 = (my + 1 < NH) ? 1.0f : 0.0f;
                const float fx0 = (mx0 >= 1) ? 1.0f : 0.0f;
                const float fx3 = (mx0 + 2 < NW) ? 1.0f : 0.0f;
                const float m00 = fy0 * fx0, m03 = fy0 * fx3;
                const float m20 = fy2 * fx0, m23 = fy2 * fx3;

                for (int c = mq; c < NC; c += 4) {
                    const float* ch = cur + (sb * NC + c) * HWSZ;
                    float a00 = __ldg(ch + oy0 + xm1) * m00;
                    float a01 = __ldg(ch + oy0 + mx0) * fy0;
                    float a02 = __ldg(ch + oy0 + mx0 + 1) * fy0;
                    float a03 = __ldg(ch + oy0 + xp2) * m03;
                    float a10 = __ldg(ch + oy1 + xm1) * fx0;
                    float a11 = __ldg(ch + oy1 + mx0);
                    float a12 = __ldg(ch + oy1 + mx0 + 1);
                    float a13 = __ldg(ch + oy1 + xp2) * fx3;
                    float a20 = __ldg(ch + oy2 + xm1) * m20;
                    float a21 = __ldg(ch + oy2 + mx0) * fy2;
                    float a22 = __ldg(ch + oy2 + mx0 + 1) * fy2;
                    float a23 = __ldg(ch + oy2 + xp2) * m23;

                    float gxA = ((a02 - a00) + 2.0f * (a12 - a10) + (a22 - a20)) * 0.125f;
                    float gxB = ((a03 - a01) + 2.0f * (a13 - a11) + (a23 - a21)) * 0.125f;
                    float gyA = ((a20 - a00) + 2.0f * (a21 - a01) + (a22 - a02)) * 0.125f;
                    float gyB = ((a21 - a01) + 2.0f * (a22 - a02) + (a23 - a03)) * 0.125f;

                    ull d;
                    PK2(d, a11, a12); pb[c] = d;
                    PK2(d, gxA, gxB); pb[17 + c] = d;
                    PK2(d, gyA, gyB); pb[34 + c] = d;

                    if (c == 16) {
                        float saA, caA, saB, caB;
                        sincosf(a11, &saA, &caA);
                        sincosf(a12, &saB, &caB);
                        ull ca2, sa2;
                        PK2(ca2, caA, caB); PK2(sa2, saA, saB);
                        pb[51] = 0ULL; pb[52] = ca2; pb[53] = sa2;
                    }
                }
            }
            __syncthreads();

            // --- cooperative MLP: thread (pair, quad), o = 4*i + quad ---
            {
                ull p2[52];
                const ulonglong2* pbr = reinterpret_cast<const ulonglong2*>(pb);
                #pragma unroll
                for (int q = 0; q < 26; q++) {
                    ulonglong2 v = pbr[q];
                    p2[2 * q] = v.x; p2[2 * q + 1] = v.y;
                }
                {
                    ull ca2 = pb[52], sa2 = pb[53];
                    float sA, sB; UPK2(sA, sB, sa2);
                    ull nsa2; PK2(nsa2, -sA, -sB);
                    #pragma unroll
                    for (int c = 0; c < NC; c++) {
                        ull gx2 = p2[17 + c], gy2 = p2[34 + c], u;
                        F2MUL2(u, ca2, gx2); F2FMA(u, sa2, gy2, u);  p2[17 + c] = u;
                        F2MUL2(u, ca2, gy2); F2FMA(u, nsa2, gx2, u); p2[34 + c] = u;
                    }
                }

                ull dx2[18];
                #pragma unroll
                for (int j = 0; j < 18; j++)
                    dx2[j] = (mq == 0) ? smem[S_B2 + j] : 0ULL;

                #pragma unroll 1
                for (int i = 0; i < 32; i++) {
                    const int o = 4 * i + mq;
                    ull acc0 = smem[S_B1 + o];
                    ull acc1 = 0ULL, acc2 = 0ULL, acc3 = 0ULL;
                    const ulonglong2* r = reinterpret_cast<const ulonglong2*>(smem + S_W1 + o * 52);
                    #pragma unroll
                    for (int q = 0; q < 13; q++) {
                        ulonglong2 wv = r[q];
                        ulonglong2 wu = r[q + 13];
                        F2FMA(acc0, wv.x, p2[2 * q],      acc0);
                        F2FMA(acc1, wv.y, p2[2 * q + 1],  acc1);
                        F2FMA(acc2, wu.x, p2[2 * q + 26], acc2);
                        F2FMA(acc3, wu.y, p2[2 * q + 27], acc3);
                    }
                    ull s02, s13, hs;
                    F2ADD(s02, acc0, acc2); F2ADD(s13, acc1, acc3); F2ADD(hs, s02, s13);
                    float hA, hB; UPK2(hA, hB, hs);
                    hA = fmaxf(hA, 0.0f); hB = fmaxf(hB, 0.0f);
                    ull h2; PK2(h2, hA, hB);

                    const ulonglong2* r2 = reinterpret_cast<const ulonglong2*>(smem + S_W2 + o * 18);
                    #pragma unroll
                    for (int q = 0; q < 9; q++) {
                        ulonglong2 wv = r2[q];
                        F2FMA(dx2[2 * q],     wv.x, h2, dx2[2 * q]);
                        F2FMA(dx2[2 * q + 1], wv.y, h2, dx2[2 * q + 1]);
                    }
                }

                #pragma unroll
                for (int j = 0; j < 18; j++) {
                    ull o2 = __shfl_down_sync(0xFFFFFFFFu, dx2[j], 2, 4);
                    F2ADD(dx2[j], dx2[j], o2);
                    o2 = __shfl_down_sync(0xFFFFFFFFu, dx2[j], 1, 4);
                    F2ADD(dx2[j], dx2[j], o2);
                }

                if (mq == 0) {
                    const float2 rr = *reinterpret_cast<const float2*>(
                        rnd_all + ((size_t)t * NB + sb) * HWSZ + mpix);
                    float mA = (rr.x < 0.5f) ? 1.0f : 0.0f;
                    float mB = (rr.y < 0.5f) ? 1.0f : 0.0f;
                    ull m2; PK2(m2, mA, mB);
                    float* dout = dst + sb * CHW + mpix;
                    #pragma unroll
                    for (int c = 0; c < NC; c++) {
                        ull nv; F2FMA(nv, dx2[c], m2, p2[c]);
                        *reinterpret_cast<ull*>(dout + c * HWSZ) = nv;
                        if (c == ALIVE_IDX)
                            *reinterpret_cast<ull*>(&g_alive[sb * HWSZ + mpix]) = nv;
                    }
                }
            }
            __syncthreads();
        }

        bsense ^= 1u; grid_barrier(bsense);

        // ========== PHASE B: alive masking (own strip, 1 pair/lane) ==========
        const bool last = (t == NSTEP - 1);
        if (sActive[w]) {
            float* dout = dst + w * CHW + opix;
            float mo[4] = {-1e30f, -1e30f, -1e30f, -1e30f};
            float mn[4] = {-1e30f, -1e30f, -1e30f, -1e30f};
            const float* oa = cur + (w * NC + ALIVE_IDX) * HWSZ;
            const unsigned naoff = w * HWSZ;
            #pragma unroll
            for (int dy = -1; dy <= 1; dy++) {
                int yy = oy + dy;
                if (yy < 0 || yy >= NH) continue;
                #pragma unroll
                for (int dxx = -1; dxx <= 2; dxx++) {
                    int xx = ox0 + dxx;
                    if (xx < 0 || xx >= NW) continue;
                    int idx = yy * NW + xx;
                    float ov = __ldg(oa + idx);
                    float nv = __ldcg(&g_alive[naoff + idx]);
                    mo[dxx + 1] = fmaxf(mo[dxx + 1], ov);
                    mn[dxx + 1] = fmaxf(mn[dxx + 1], nv);
                }
            }
            float moA = fmaxf(fmaxf(mo[0], mo[1]), mo[2]);
            float moB = fmaxf(fmaxf(mo[1], mo[2]), mo[3]);
            float mnA = fmaxf(fmaxf(mn[0], mn[1]), mn[2]);
            float mnB = fmaxf(fmaxf(mn[1], mn[2]), mn[3]);
            const bool aliveA = (moA > ALIVE_THR) && (mnA > ALIVE_THR);
            const bool aliveB = (moB > ALIVE_THR) && (mnB > ALIVE_THR);

            if (!aliveA && !aliveB) {
                #pragma unroll
                for (int c = 0; c < NC; c++)
                    *reinterpret_cast<ull*>(dout + c * HWSZ) = 0ULL;
            } else if (!aliveA) {
                #pragma unroll
                for (int c = 0; c < NC; c++) dout[c * HWSZ] = 0.0f;
            } else if (!aliveB) {
                #pragma unroll
                for (int c = 0; c < NC; c++) dout[c * HWSZ + 1] = 0.0f;
            }
            uchar2 am; am.x = aliveA ? 1 : 0; am.y = aliveB ? 1 : 0;
            *reinterpret_cast<uchar2*>(&g_amask[w * HWSZ + opix]) = am;

            if (last && (aliveA || aliveB)) {
                #pragma unroll
                for (int c = 0; c < 4; c++) {
                    float vA = aliveA ? dout[c * HWSZ]     : 0.0f;
                    float vB = aliveB ? dout[c * HWSZ + 1] : 0.0f;
                    float2 fv; fv.x = vA; fv.y = vB;
                    *reinterpret_cast<float2*>(final_out + (w * 4 + c) * HWSZ + opix) = fv;
                }
            }
        }

        bsense ^= 1u; grid_barrier(bsense);
        cur = dst;
    }
}

// ---------------------------------------------------------------------------
// Inputs: 0 init_state [4,17,128,128], 1 rand [48,4,1,128,128],
//         2 W1 [128,51], 3 b1 [128], 4 W2 [17,128], 5 b2 [17]
// Output f32: final[:, :4] (262144) then dev_path (48*4*17*128*128).
// ---------------------------------------------------------------------------
extern "C" void kernel_launch(void* const* d_in, const int* in_sizes, int n_in,
                              void* d_out, int out_size)
{
    const float* init_state = (const float*)d_in[0];
    const float* rnd        = (const float*)d_in[1];
    const float* W1         = (const float*)d_in[2];
    const float* b1         = (const float*)d_in[3];
    const float* W2         = (const float*)d_in[4];
    const float* b2         = (const float*)d_in[5];

    float* out      = (float*)d_out;
    float* final_p  = out;
    float* dev_path = out + FINAL_ELEMS;

    cudaMemsetAsync(d_out, 0, (size_t)out_size * sizeof(float));

    cudaFuncSetAttribute(nca_persistent,
                         cudaFuncAttributeMaxDynamicSharedMemorySize, SMEM_BYTES);

    nca_persistent<<<NBLK, 128, SMEM_BYTES>>>(init_state, rnd, W1, b1, W2, b2,
                                              dev_path, final_p);
}

// round 14
// speedup vs baseline: 1.4069x; 1.0600x over previous
#include <cuda_runtime.h>
#include <math.h>

// Problem constants
#define NB    4
#define NC    17
#define NH    128
#define NW    128
#define HWSZ  (NH*NW)
#define NPC   51
#define NWID  128
#define NSTEP 48
#define ALIVE_IDX 3
#define ALIVE_THR 0.1f

#define CHW   (NC*HWSZ)
#define BCHW  (NB*CHW)
#define FINAL_ELEMS (NB*4*HWSZ)
#define NBLK  256

typedef unsigned long long ull;

// f32x2 packed-pair helpers
#define F2FMA(d, a, b, c) asm("fma.rn.f32x2 %0, %1, %2, %3;" : "=l"(d) : "l"(a), "l"(b), "l"(c))
#define F2MUL2(d, a, b)   asm("mul.rn.f32x2 %0, %1, %2;"     : "=l"(d) : "l"(a), "l"(b))
#define F2ADD(d, a, b)    asm("add.rn.f32x2 %0, %1, %2;"     : "=l"(d) : "l"(a), "l"(b))
#define PK2(d, lo, hi)    asm("mov.b64 %0, {%1, %2};" : "=l"(d) : "f"(lo), "f"(hi))
#define UPK2(lo, hi, s)   asm("mov.b64 {%0, %1}, %2;" : "=f"(lo), "=f"(hi) : "l"(s))

// Static device scratch
__device__ float         g_alive[NB * HWSZ];   // unmasked new alive channel
__device__ unsigned char g_amask[NB * HWSZ];   // per-pixel alive map (post-mask)
__device__ unsigned      g_count;
__device__ volatile unsigned g_sense;

// R7 flat barrier verbatim (nanosleep spin — proven).
__device__ __forceinline__ void grid_barrier(unsigned target) {
    __syncthreads();
    if (threadIdx.x == 0) {
        __threadfence();
        if (atomicAdd(&g_count, 1u) == NBLK - 1u) {
            g_count = 0u;
            __threadfence();
            g_sense = target;
        } else {
            while (g_sense != target) __nanosleep(32);
            __threadfence();
        }
    }
    __syncthreads();
}

// Dynamic smem layout (ull units)
#define S_W1  0                      // 128 rows x 52 dup W1
#define S_W2  (S_W1 + 128*52)        // 128 rows x 18 dup W2^T
#define S_B1  (S_W2 + 128*18)        // 128 dup b1
#define S_B2  (S_B1 + 128)           // 18 dup b2
#define S_PB  (S_B2 + 20)            // 32 pairs x 54 p-vector buffer
#define PBS   54
#define SMEM_ULLS (S_PB + 32*PBS)
#define SMEM_BYTES (SMEM_ULLS * 8)

__global__ __launch_bounds__(128, 2)
void nca_persistent(const float* __restrict__ init_state,
                    const float* __restrict__ rnd_all,
                    const float* __restrict__ W1, const float* __restrict__ b1,
                    const float* __restrict__ W2, const float* __restrict__ b2,
                    float* __restrict__ dev_path,   // [48,B,C,H,W] (pre-zeroed)
                    float* __restrict__ final_out)  // [B,4,H,W]   (pre-zeroed)
{
    extern __shared__ ull smem[];
    __shared__ int sActive[4];
    const int tid = threadIdx.x;

    // ---- load duplicated weights once (R7 verbatim) ----
    for (int i = tid; i < 128 * 52; i += 128) {
        int o = i / 52, c = i - o * 52;
        float wv = (c < NPC) ? W1[o * NPC + c] : 0.0f;
        ull d; PK2(d, wv, wv); smem[S_W1 + i] = d;
    }
    for (int i = tid; i < 128 * 18; i += 128) {
        int o = i / 18, j = i - o * 18;
        float wv = (j < NC) ? W2[j * NWID + o] : 0.0f;
        ull d; PK2(d, wv, wv); smem[S_W2 + i] = d;
    }
    { float wv = b1[tid]; ull d; PK2(d, wv, wv); smem[S_B1 + tid] = d; }
    if (tid < 18) { float wv = (tid < NC) ? b2[tid] : 0.0f; ull d; PK2(d, wv, wv); smem[S_B2 + tid] = d; }

    int bias_ok = (b1[tid] <= 0.0f);
    if (tid < NC) bias_ok = bias_ok && (b2[tid] == 0.0f);
    const int allz = __syncthreads_and(bias_ok);

    // ---- VERTICAL strip interleaving (the single change vs R7) ----
    // Warp w of block bid owns strip (batch = bid>>6,
    //   region = ((bid&63) + 64*w) & 255)  -> block's 4 strips are 32 px apart
    // vertically, so a ~20px blob activates at most ONE strip per block.
    const int bid  = blockIdx.x;
    const int b    = bid >> 6;
    const int tle  = bid & 63;
    const int w    = tid >> 5;
    const int lane = tid & 31;

    const int orr  = (tle + 64 * w) & 255;   // own region index
    const int osrx = orr & 7;                // region col 0..7
    const int osry = orr >> 3;               // region row 0..31
    const int obx0 = osrx * 16;
    const int osy0 = osry * 4;

    // own-strip pixel mapping: 32 lanes = 8 pair-cols x 4 rows
    const int opr = lane & 7, oly = lane >> 3;
    const int ox0 = obx0 + opr * 2;
    const int oy  = osy0 + oly;
    const int opix = oy * NW + ox0;

    // cooperative mapping for A2: pair 0..31, quad 0..3
    const int mpair = tid >> 2, mq = tid & 3;
    const int mpr = mpair & 7, mply = mpair >> 3;

    unsigned bsense = 0;
    const float* cur = init_state;

    #pragma unroll 1
    for (int t = 0; t < NSTEP; t++) {
        float* dst = dev_path + (size_t)t * BCHW;

        // ========== PHASE A1: per-warp skip check (own strip) ==========
        bool skipped = false;
        if (t > 0 && allz) {
            // 18x6 alive-map halo of own strip
            const int hx0 = obx0 - 1, hy0 = osy0 - 1;
            unsigned v = 0;
            #pragma unroll
            for (int k = 0; k < 4; k++) {
                int i = lane + 32 * k;
                if (i < 108) {
                    int hx = hx0 + (i % 18);
                    int hy = hy0 + (i / 18);
                    if (hx >= 0 && hx < NW && hy >= 0 && hy < NH)
                        v |= __ldcg(&g_amask[b * HWSZ + hy * NW + hx]);
                }
            }
            skipped = !__any_sync(0xFFFFFFFFu, v != 0);
        }
        if (lane == 0) sActive[w] = skipped ? 0 : 1;
        if (skipped) {
            *reinterpret_cast<ull*>(&g_alive[b * HWSZ + opix]) = 0ULL;
            uchar2 z; z.x = 0; z.y = 0;
            *reinterpret_cast<uchar2*>(&g_amask[b * HWSZ + opix]) = z;
        }
        __syncthreads();

        // ========== PHASE A2: cooperative compute of active strips ==========
        #pragma unroll 1
        for (int s = 0; s < 4; s++) {
            if (!sActive[s]) continue;
            const int sr   = (tle + 64 * s) & 255;
            const int sbx0 = (sr & 7) * 16;
            const int ssy0 = (sr >> 3) * 4;

            const int mx0  = sbx0 + mpr * 2;
            const int my   = ssy0 + mply;
            const int mpix = my * NW + mx0;
            ull* pb = smem + S_PB + mpair * PBS;

            // --- cooperative conv: 4 threads/pair, channels mq,mq+4,... ---
            {
                const int xm1 = (mx0 >= 1) ? mx0 - 1 : 0;
                const int xp2 = (mx0 + 2 < NW) ? mx0 + 2 : NW - 1;
                const int ym1 = (my >= 1) ? my - 1 : 0;
                const int yp1 = (my + 1 < NH) ? my + 1 : NH - 1;
                const int oy0 = ym1 * NW, oy1 = my * NW, oy2 = yp1 * NW;
                const float fy0 = (my >= 1) ? 1.0f : 0.0f;
                const float fy2 = (my + 1 < NH) ? 1.0f : 0.0f;
                const float fx0 = (mx0 >= 1) ? 1.0f : 0.0f;
                const float fx3 = (mx0 + 2 < NW) ? 1.0f : 0.0f;
                const float m00 = fy0 * fx0, m03 = fy0 * fx3;
                const float m20 = fy2 * fx0, m23 = fy2 * fx3;

                for (int c = mq; c < NC; c += 4) {
                    const float* ch = cur + (b * NC + c) * HWSZ;
                    float a00 = __ldg(ch + oy0 + xm1) * m00;
                    float a01 = __ldg(ch + oy0 + mx0) * fy0;
                    float a02 = __ldg(ch + oy0 + mx0 + 1) * fy0;
                    float a03 = __ldg(ch + oy0 + xp2) * m03;
                    float a10 = __ldg(ch + oy1 + xm1) * fx0;
                    float a11 = __ldg(ch + oy1 + mx0);
                    float a12 = __ldg(ch + oy1 + mx0 + 1);
                    float a13 = __ldg(ch + oy1 + xp2) * fx3;
                    float a20 = __ldg(ch + oy2 + xm1) * m20;
                    float a21 = __ldg(ch + oy2 + mx0) * fy2;
                    float a22 = __ldg(ch + oy2 + mx0 + 1) * fy2;
                    float a23 = __ldg(ch + oy2 + xp2) * m23;

                    float gxA = ((a02 - a00) + 2.0f * (a12 - a10) + (a22 - a20)) * 0.125f;
                    float gxB = ((a03 - a01) + 2.0f * (a13 - a11) + (a23 - a21)) * 0.125f;
                    float gyA = ((a20 - a00) + 2.0f * (a21 - a01) + (a22 - a02)) * 0.125f;
                    float gyB = ((a21 - a01) + 2.0f * (a22 - a02) + (a23 - a03)) * 0.125f;

                    ull d;
                    PK2(d, a11, a12); pb[c] = d;
                    PK2(d, gxA, gxB); pb[17 + c] = d;
                    PK2(d, gyA, gyB); pb[34 + c] = d;

                    if (c == 16) {
                        float saA, caA, saB, caB;
                        sincosf(a11, &saA, &caA);
                        sincosf(a12, &saB, &caB);
                        ull ca2, sa2;
                        PK2(ca2, caA, caB); PK2(sa2, saA, saB);
                        pb[51] = 0ULL; pb[52] = ca2; pb[53] = sa2;
                    }
                }
            }
            __syncthreads();

            // --- cooperative MLP: thread (pair, quad), o = 4*i + quad ---
            {
                ull p2[52];
                const ulonglong2* pbr = reinterpret_cast<const ulonglong2*>(pb);
                #pragma unroll
                for (int q = 0; q < 26; q++) {
                    ulonglong2 v = pbr[q];
                    p2[2 * q] = v.x; p2[2 * q + 1] = v.y;
                }
                {
                    ull ca2 = pb[52], sa2 = pb[53];
                    float sA, sB; UPK2(sA, sB, sa2);
                    ull nsa2; PK2(nsa2, -sA, -sB);
                    #pragma unroll
                    for (int c = 0; c < NC; c++) {
                        ull gx2 = p2[17 + c], gy2 = p2[34 + c], u;
                        F2MUL2(u, ca2, gx2); F2FMA(u, sa2, gy2, u);  p2[17 + c] = u;
                        F2MUL2(u, ca2, gy2); F2FMA(u, nsa2, gx2, u); p2[34 + c] = u;
                    }
                }

                ull dx2[18];
                #pragma unroll
                for (int j = 0; j < 18; j++)
                    dx2[j] = (mq == 0) ? smem[S_B2 + j] : 0ULL;

                #pragma unroll 1
                for (int i = 0; i < 32; i++) {
                    const int o = 4 * i + mq;
                    ull acc0 = smem[S_B1 + o];
                    ull acc1 = 0ULL, acc2 = 0ULL, acc3 = 0ULL;
                    const ulonglong2* r = reinterpret_cast<const ulonglong2*>(smem + S_W1 + o * 52);
                    #pragma unroll
                    for (int q = 0; q < 13; q++) {
                        ulonglong2 wv = r[q];
                        ulonglong2 wu = r[q + 13];
                        F2FMA(acc0, wv.x, p2[2 * q],      acc0);
                        F2FMA(acc1, wv.y, p2[2 * q + 1],  acc1);
                        F2FMA(acc2, wu.x, p2[2 * q + 26], acc2);
                        F2FMA(acc3, wu.y, p2[2 * q + 27], acc3);
                    }
                    ull s02, s13, hs;
                    F2ADD(s02, acc0, acc2); F2ADD(s13, acc1, acc3); F2ADD(hs, s02, s13);
                    float hA, hB; UPK2(hA, hB, hs);
                    hA = fmaxf(hA, 0.0f); hB = fmaxf(hB, 0.0f);
                    ull h2; PK2(h2, hA, hB);

                    const ulonglong2* r2 = reinterpret_cast<const ulonglong2*>(smem + S_W2 + o * 18);
                    #pragma unroll
                    for (int q = 0; q < 9; q++) {
                        ulonglong2 wv = r2[q];
                        F2FMA(dx2[2 * q],     wv.x, h2, dx2[2 * q]);
                        F2FMA(dx2[2 * q + 1], wv.y, h2, dx2[2 * q + 1]);
                    }
                }

                #pragma unroll
                for (int j = 0; j < 18; j++) {
                    ull o2 = __shfl_down_sync(0xFFFFFFFFu, dx2[j], 2, 4);
                    F2ADD(dx2[j], dx2[j], o2);
                    o2 = __shfl_down_sync(0xFFFFFFFFu, dx2[j], 1, 4);
                    F2ADD(dx2[j], dx2[j], o2);
                }

                if (mq == 0) {
                    const float2 rr = *reinterpret_cast<const float2*>(
                        rnd_all + ((size_t)t * NB + b) * HWSZ + mpix);
                    float mA = (rr.x < 0.5f) ? 1.0f : 0.0f;
                    float mB = (rr.y < 0.5f) ? 1.0f : 0.0f;
                    ull m2; PK2(m2, mA, mB);
                    float* dout = dst + b * CHW + mpix;
                    #pragma unroll
                    for (int c = 0; c < NC; c++) {
                        ull nv; F2FMA(nv, dx2[c], m2, p2[c]);
                        *reinterpret_cast<ull*>(dout + c * HWSZ) = nv;
                        if (c == ALIVE_IDX)
                            *reinterpret_cast<ull*>(&g_alive[b * HWSZ + mpix]) = nv;
                    }
                }
            }
            __syncthreads();
        }

        bsense ^= 1u; grid_barrier(bsense);

        // ========== PHASE B: alive masking (own strip, 1 pair/lane) ==========
        const bool last = (t == NSTEP - 1);
        if (sActive[w]) {
            float* dout = dst + b * CHW + opix;
            float mo[4] = {-1e30f, -1e30f, -1e30f, -1e30f};
            float mn[4] = {-1e30f, -1e30f, -1e30f, -1e30f};
            const float* oa = cur + (b * NC + ALIVE_IDX) * HWSZ;
            const unsigned naoff = b * HWSZ;
            #pragma unroll
            for (int dy = -1; dy <= 1; dy++) {
                int yy = oy + dy;
                if (yy < 0 || yy >= NH) continue;
                #pragma unroll
                for (int dxx = -1; dxx <= 2; dxx++) {
                    int xx = ox0 + dxx;
                    if (xx < 0 || xx >= NW) continue;
                    int idx = yy * NW + xx;
                    float ov = __ldg(oa + idx);
                    float nv = __ldcg(&g_alive[naoff + idx]);
                    mo[dxx + 1] = fmaxf(mo[dxx + 1], ov);
                    mn[dxx + 1] = fmaxf(mn[dxx + 1], nv);
                }
            }
            float moA = fmaxf(fmaxf(mo[0], mo[1]), mo[2]);
            float moB = fmaxf(fmaxf(mo[1], mo[2]), mo[3]);
            float mnA = fmaxf(fmaxf(mn[0], mn[1]), mn[2]);
            float mnB = fmaxf(fmaxf(mn[1], mn[2]), mn[3]);
            const bool aliveA = (moA > ALIVE_THR) && (mnA > ALIVE_THR);
            const bool aliveB = (moB > ALIVE_THR) && (mnB > ALIVE_THR);

            if (!aliveA && !aliveB) {
                #pragma unroll
                for (int c = 0; c < NC; c++)
                    *reinterpret_cast<ull*>(dout + c * HWSZ) = 0ULL;
            } else if (!aliveA) {
                #pragma unroll
                for (int c = 0; c < NC; c++) dout[c * HWSZ] = 0.0f;
            } else if (!aliveB) {
                #pragma unroll
                for (int c = 0; c < NC; c++) dout[c * HWSZ + 1] = 0.0f;
            }
            uchar2 am; am.x = aliveA ? 1 : 0; am.y = aliveB ? 1 : 0;
            *reinterpret_cast<uchar2*>(&g_amask[b * HWSZ + opix]) = am;

            if (last && (aliveA || aliveB)) {
                #pragma unroll
                for (int c = 0; c < 4; c++) {
                    float vA = aliveA ? dout[c * HWSZ]     : 0.0f;
                    float vB = aliveB ? dout[c * HWSZ + 1] : 0.0f;
                    float2 fv; fv.x = vA; fv.y = vB;
                    *reinterpret_cast<float2*>(final_out + (b * 4 + c) * HWSZ + opix) = fv;
                }
            }
        }

        bsense ^= 1u; grid_barrier(bsense);
        cur = dst;
    }
}

// ---------------------------------------------------------------------------
// Inputs: 0 init_state [4,17,128,128], 1 rand [48,4,1,128,128],
//         2 W1 [128,51], 3 b1 [128], 4 W2 [17,128], 5 b2 [17]
// Output f32: final[:, :4] (262144) then dev_path (48*4*17*128*128).
// ---------------------------------------------------------------------------
extern "C" void kernel_launch(void* const* d_in, const int* in_sizes, int n_in,
                              void* d_out, int out_size)
{
    const float* init_state = (const float*)d_in[0];
    const float* rnd        = (const float*)d_in[1];
    const float* W1         = (const float*)d_in[2];
    const float* b1         = (const float*)d_in[3];
    const float* W2         = (const float*)d_in[4];
    const float* b2         = (const float*)d_in[5];

    float* out      = (float*)d_out;
    float* final_p  = out;
    float* dev_path = out + FINAL_ELEMS;

    cudaMemsetAsync(d_out, 0, (size_t)out_size * sizeof(float));

    cudaFuncSetAttribute(nca_persistent,
                         cudaFuncAttributeMaxDynamicSharedMemorySize, SMEM_BYTES);

    nca_persistent<<<NBLK, 128, SMEM_BYTES>>>(init_state, rnd, W1, b1, W2, b2,
                                              dev_path, final_p);
}